// round 2
// baseline (speedup 1.0000x reference)
#include <cuda_runtime.h>
#include <cstdint>
#include <cstddef>

#define NSTEP 32768
#define HH 128
#define G3 384
#define KDIM 530
#define EDIM 512
#define ADIM 18
#define FCDIM 256

__device__ float g_gi_pred[(size_t)NSTEP * G3];
__device__ float g_gi_true[(size_t)NSTEP * G3];
__device__ float g_hpred[(size_t)NSTEP * HH];

typedef unsigned long long ull;

__device__ __forceinline__ ull ffma2(ull a, ull b, ull c) {
    ull d;
    asm("fma.rn.f32x2 %0, %1, %2, %3;" : "=l"(d) : "l"(a), "l"(b), "l"(c));
    return d;
}
__device__ __forceinline__ float plo(ull a) { return __uint_as_float((unsigned)a); }
__device__ __forceinline__ float phi(ull a) { return __uint_as_float((unsigned)(a >> 32)); }
__device__ __forceinline__ float sigf(float x) { return 1.f / (1.f + __expf(-x)); }

__device__ __forceinline__ void cpa4(unsigned dst, const float* src) {
    asm volatile("cp.async.ca.shared.global [%0], [%1], 4;" :: "r"(dst), "l"(src));
}
#define CP_COMMIT() asm volatile("cp.async.commit_group;")
#define CP_WAIT1()  asm volatile("cp.async.wait_group 1;" ::: "memory")

// ============================================================================
// Kernel 1: gi = concat(enc, act) @ Wih.T + bih  (z=0: pred, z=1: true)
// M=32768 N=384 K=530. BM=BN=64 BK=16, 256 thr, 4x4 micro-tile.
// ============================================================================
__global__ void __launch_bounds__(256) gi_gemm(
    const float* __restrict__ encp, const float* __restrict__ enct,
    const float* __restrict__ act,  const float* __restrict__ Wih,
    const float* __restrict__ bih)
{
    const float* A = blockIdx.z ? enct : encp;
    float* C = blockIdx.z ? g_gi_true : g_gi_pred;

    __shared__ __align__(16) float As[16][68];
    __shared__ __align__(16) float Bs[16][68];

    int t = threadIdx.x;
    int m0 = blockIdx.x * 64, n0 = blockIdx.y * 64;
    int tx = t & 15, ty = t >> 4;
    int arow = t >> 2, ac4 = (t & 3) * 4;

    float acc[4][4];
#pragma unroll
    for (int a = 0; a < 4; a++)
#pragma unroll
        for (int b = 0; b < 4; b++) acc[a][b] = 0.f;

    for (int kt = 0; kt < 34; kt++) {
        int k0 = kt * 16;
        float av[4], bv[4];
        if (k0 < EDIM) {
            float4 v = *(const float4*)(A + (size_t)(m0 + arow) * EDIM + k0 + ac4);
            av[0] = v.x; av[1] = v.y; av[2] = v.z; av[3] = v.w;
            const float* bp = Wih + (size_t)(n0 + arow) * KDIM + k0 + ac4;
            float2 u0 = *(const float2*)(bp);
            float2 u1 = *(const float2*)(bp + 2);
            bv[0] = u0.x; bv[1] = u0.y; bv[2] = u1.x; bv[3] = u1.y;
        } else {
#pragma unroll
            for (int j = 0; j < 4; j++) {
                int kg = k0 + ac4 + j;
                av[j] = (kg < KDIM) ? act[(size_t)(m0 + arow) * ADIM + (kg - EDIM)] : 0.f;
                bv[j] = (kg < KDIM) ? Wih[(size_t)(n0 + arow) * KDIM + kg] : 0.f;
            }
        }
        __syncthreads();
#pragma unroll
        for (int j = 0; j < 4; j++) { As[ac4 + j][arow] = av[j]; Bs[ac4 + j][arow] = bv[j]; }
        __syncthreads();
#pragma unroll
        for (int kk = 0; kk < 16; kk++) {
            float4 a4 = *(const float4*)&As[kk][ty * 4];
            float4 b4 = *(const float4*)&Bs[kk][tx * 4];
            float ar[4] = {a4.x, a4.y, a4.z, a4.w};
            float br[4] = {b4.x, b4.y, b4.z, b4.w};
#pragma unroll
            for (int r = 0; r < 4; r++)
#pragma unroll
                for (int cc = 0; cc < 4; cc++) acc[r][cc] += ar[r] * br[cc];
        }
    }
#pragma unroll
    for (int r = 0; r < 4; r++) {
        int m = m0 + ty * 4 + r;
#pragma unroll
        for (int cc = 0; cc < 4; cc++) {
            int n = n0 + tx * 4 + cc;
            C[(size_t)m * G3 + n] = acc[r][cc] + bih[n];
        }
    }
}

// ============================================================================
// Kernel 2: sequential GRU scan, 32768 steps, 1 persistent CTA, 512 threads.
// Thread (i=t>>2, c=t&3) owns Whh rows {i,128+i,256+i} cols {16q+4c..+3}.
// Packed FFMA2 matvec; quad shfl reduce; cp.async gi prefetch 2 steps ahead.
// ============================================================================
__global__ void __launch_bounds__(512, 1) gru_scan(
    const float* __restrict__ Whh, const float* __restrict__ bhh,
    const float* __restrict__ h0)
{
    __shared__ __align__(16) float hbuf[2][HH];
    __shared__ __align__(16) float gbuf[4][6 * HH];

    int t = threadIdx.x;
    int i = t >> 2;
    int c = t & 3;

    ull wr[16], wz[16], wn[16];
#pragma unroll
    for (int q = 0; q < 8; q++) {
        int col = 16 * q + 4 * c;
        const ull* pr = (const ull*)(Whh + (size_t)i * HH + col);
        const ull* pz = (const ull*)(Whh + (size_t)(HH + i) * HH + col);
        const ull* pn = (const ull*)(Whh + (size_t)(2 * HH + i) * HH + col);
        wr[2 * q] = pr[0]; wr[2 * q + 1] = pr[1];
        wz[2 * q] = pz[0]; wz[2 * q + 1] = pz[1];
        wn[2 * q] = pn[0]; wn[2 * q + 1] = pn[1];
    }
    float br = bhh[i], bz = bhh[HH + i], bn = bhh[2 * HH + i];
    if (t < HH) hbuf[0][t] = h0[t];

    const float* srcbase = (c == 0) ? (g_gi_pred + i) : (g_gi_true + i);
    int gofs = (c == 0) ? 0 : 3;
    unsigned gdst0 = (unsigned)__cvta_generic_to_shared(&gbuf[0][gofs * HH + i]);
    bool loader = (c < 2);
    const unsigned BUFSTRIDE = 6 * HH * 4;

    if (loader) { cpa4(gdst0, srcbase); cpa4(gdst0 + 512, srcbase + HH); cpa4(gdst0 + 1024, srcbase + 2 * HH); }
    CP_COMMIT();
    if (loader) {
        const float* s1 = srcbase + G3;
        unsigned d1 = gdst0 + BUFSTRIDE;
        cpa4(d1, s1); cpa4(d1 + 512, s1 + HH); cpa4(d1 + 1024, s1 + 2 * HH);
    }
    CP_COMMIT();
    CP_WAIT1();
    __syncthreads();

    const float* srcnext = srcbase + 2 * (size_t)G3;
    int p = 0;

    for (int s = 0; s < NSTEP; s++) {
        if (loader && (s + 2) < NSTEP) {
            unsigned d = gdst0 + (unsigned)((s + 2) & 3) * BUFSTRIDE;
            cpa4(d, srcnext); cpa4(d + 512, srcnext + HH); cpa4(d + 1024, srcnext + 2 * HH);
        }
        CP_COMMIT();
        srcnext += G3;

        const ulonglong2* hp2 = ((const ulonglong2*)hbuf[p]) + c;
        ull ar = 0, az = 0, an = 0;
#pragma unroll
        for (int q = 0; q < 8; q++) {
            ulonglong2 hq = hp2[4 * q];
            ar = ffma2(wr[2 * q], hq.x, ar);
            az = ffma2(wz[2 * q], hq.x, az);
            an = ffma2(wn[2 * q], hq.x, an);
            ar = ffma2(wr[2 * q + 1], hq.y, ar);
            az = ffma2(wz[2 * q + 1], hq.y, az);
            an = ffma2(wn[2 * q + 1], hq.y, an);
        }
        float sr = plo(ar) + phi(ar);
        float sz = plo(az) + phi(az);
        float sn = plo(an) + phi(an);
        sr += __shfl_xor_sync(0xffffffffu, sr, 1);
        sz += __shfl_xor_sync(0xffffffffu, sz, 1);
        sn += __shfl_xor_sync(0xffffffffu, sn, 1);
        sr += __shfl_xor_sync(0xffffffffu, sr, 2);
        sz += __shfl_xor_sync(0xffffffffu, sz, 2);
        sn += __shfl_xor_sync(0xffffffffu, sn, 2);

        if (c == 0) {
            const float* gb = gbuf[s & 3];
            float ghr = sr + br, ghz = sz + bz, ghn = sn + bn;
            float hprev = hbuf[p][i];
            float r1 = sigf(gb[i] + ghr);
            float z1 = sigf(gb[HH + i] + ghz);
            float n1 = tanhf(gb[2 * HH + i] + r1 * ghn);
            g_hpred[(size_t)s * HH + i] = (1.f - z1) * n1 + z1 * hprev;
            float r2 = sigf(gb[3 * HH + i] + ghr);
            float z2 = sigf(gb[4 * HH + i] + ghz);
            float n2 = tanhf(gb[5 * HH + i] + r2 * ghn);
            hbuf[p ^ 1][i] = (1.f - z2) * n2 + z2 * hprev;
        }
        CP_WAIT1();
        __syncthreads();
        p ^= 1;
    }
}

// ============================================================================
// Kernel 3: MLP head. 512 CTAs x 256 thr; 64 rows/CTA; fc1w smem-resident.
// ============================================================================
__global__ void __launch_bounds__(256) mlp_head(
    const float* __restrict__ fc1w, const float* __restrict__ fc1b,
    const float* __restrict__ fc2w, const float* __restrict__ fc2b,
    float* __restrict__ out)
{
    extern __shared__ float sm[];
    float* w1  = sm;
    float* b1  = sm + FCDIM * HH;
    float* w2  = b1 + FCDIM;
    float* hs  = w2 + FCDIM;
    float* red = hs + HH;

    int t = threadIdx.x;
    for (int idx = t; idx < FCDIM * HH; idx += 256) w1[idx] = fc1w[idx];
    b1[t] = fc1b[t];
    w2[t] = fc2w[t];
    __syncthreads();

    float myb = b1[t], myw2 = w2[t];
    const float4* wj = (const float4*)(w1 + t * HH);

    for (int r = 0; r < 64; r++) {
        size_t row = (size_t)blockIdx.x * 64 + r;
        if (t < HH) hs[t] = g_hpred[row * HH + t];
        __syncthreads();
        float acc = 0.f;
        const float4* hv = (const float4*)hs;
#pragma unroll
        for (int q = 0; q < 32; q++) {
            float4 a = wj[q], b = hv[q];
            acc += a.x * b.x; acc += a.y * b.y; acc += a.z * b.z; acc += a.w * b.w;
        }
        float v = acc + myb;
        v = v > 0.f ? v : 0.f;
        v *= myw2;
#pragma unroll
        for (int m = 16; m; m >>= 1) v += __shfl_xor_sync(0xffffffffu, v, m);
        if ((t & 31) == 0) red[t >> 5] = v;
        __syncthreads();
        if (t == 0) {
            float sv = red[0] + red[1] + red[2] + red[3] +
                       red[4] + red[5] + red[6] + red[7] + fc2b[0];
            out[row] = 1.f / (1.f + __expf(-sv));
        }
        __syncthreads();
    }
}

extern "C" void kernel_launch(void* const* d_in, const int* in_sizes, int n_in,
                              void* d_out, int out_size) {
    const float* enc  = (const float*)d_in[0];
    const float* act  = (const float*)d_in[1];
    const float* tru  = (const float*)d_in[2];
    const float* Wih  = (const float*)d_in[3];
    const float* Whh  = (const float*)d_in[4];
    const float* bih  = (const float*)d_in[5];
    const float* bhh  = (const float*)d_in[6];
    const float* h0   = (const float*)d_in[7];
    const float* fc1w = (const float*)d_in[8];
    const float* fc1b = (const float*)d_in[9];
    const float* fc2w = (const float*)d_in[10];
    const float* fc2b = (const float*)d_in[11];
    float* out = (float*)d_out;

    int mlp_smem = (FCDIM * HH + FCDIM + FCDIM + HH + 8) * 4;
    cudaFuncSetAttribute(mlp_head, cudaFuncAttributeMaxDynamicSharedMemorySize, mlp_smem);

    dim3 g(512, 6, 2);
    gi_gemm<<<g, 256>>>(enc, tru, act, Wih, bih);
    gru_scan<<<1, 512>>>(Whh, bhh, h0);
    mlp_head<<<512, 256, mlp_smem>>>(fc1w, fc1b, fc2w, fc2b, out);
}

// round 3
// speedup vs baseline: 1.6880x; 1.6880x over previous
#include <cuda_runtime.h>
#include <cstdint>
#include <cstddef>

#define NSTEP 32768
#define HH 128
#define G3 384
#define KDIM 530
#define EDIM 512
#define ADIM 18
#define FCDIM 256

__device__ float g_gi_pred[(size_t)NSTEP * G3];
__device__ float g_gi_true[(size_t)NSTEP * G3];
__device__ float g_hpred[(size_t)NSTEP * HH];

typedef unsigned long long ull;

__device__ __forceinline__ ull ffma2(ull a, ull b, ull c) {
    ull d;
    asm("fma.rn.f32x2 %0, %1, %2, %3;" : "=l"(d) : "l"(a), "l"(b), "l"(c));
    return d;
}
__device__ __forceinline__ float plo(ull a) { return __uint_as_float((unsigned)a); }
__device__ __forceinline__ float phi(ull a) { return __uint_as_float((unsigned)(a >> 32)); }
__device__ __forceinline__ float sigf(float x) {
    return __fdividef(1.f, 1.f + __expf(-x));
}
__device__ __forceinline__ float tanhf_fast(float x) {
    return __fdividef(2.f, 1.f + __expf(-2.f * x)) - 1.f;
}

__device__ __forceinline__ void cpa4(unsigned dst, const float* src) {
    asm volatile("cp.async.ca.shared.global [%0], [%1], 4;" :: "r"(dst), "l"(src));
}
#define CP_COMMIT() asm volatile("cp.async.commit_group;")
#define CP_WAIT3()  asm volatile("cp.async.wait_group 3;" ::: "memory")

// ============================================================================
// Kernel 1: gi = concat(enc, act) @ Wih.T + bih  (z=0: pred, z=1: true)
// M=32768 N=384 K=530. BM=BN=64 BK=16, 256 thr, 4x4 micro-tile. (unchanged)
// ============================================================================
__global__ void __launch_bounds__(256) gi_gemm(
    const float* __restrict__ encp, const float* __restrict__ enct,
    const float* __restrict__ act,  const float* __restrict__ Wih,
    const float* __restrict__ bih)
{
    const float* A = blockIdx.z ? enct : encp;
    float* C = blockIdx.z ? g_gi_true : g_gi_pred;

    __shared__ __align__(16) float As[16][68];
    __shared__ __align__(16) float Bs[16][68];

    int t = threadIdx.x;
    int m0 = blockIdx.x * 64, n0 = blockIdx.y * 64;
    int tx = t & 15, ty = t >> 4;
    int arow = t >> 2, ac4 = (t & 3) * 4;

    float acc[4][4];
#pragma unroll
    for (int a = 0; a < 4; a++)
#pragma unroll
        for (int b = 0; b < 4; b++) acc[a][b] = 0.f;

    for (int kt = 0; kt < 34; kt++) {
        int k0 = kt * 16;
        float av[4], bv[4];
        if (k0 < EDIM) {
            float4 v = *(const float4*)(A + (size_t)(m0 + arow) * EDIM + k0 + ac4);
            av[0] = v.x; av[1] = v.y; av[2] = v.z; av[3] = v.w;
            const float* bp = Wih + (size_t)(n0 + arow) * KDIM + k0 + ac4;
            float2 u0 = *(const float2*)(bp);
            float2 u1 = *(const float2*)(bp + 2);
            bv[0] = u0.x; bv[1] = u0.y; bv[2] = u1.x; bv[3] = u1.y;
        } else {
#pragma unroll
            for (int j = 0; j < 4; j++) {
                int kg = k0 + ac4 + j;
                av[j] = (kg < KDIM) ? act[(size_t)(m0 + arow) * ADIM + (kg - EDIM)] : 0.f;
                bv[j] = (kg < KDIM) ? Wih[(size_t)(n0 + arow) * KDIM + kg] : 0.f;
            }
        }
        __syncthreads();
#pragma unroll
        for (int j = 0; j < 4; j++) { As[ac4 + j][arow] = av[j]; Bs[ac4 + j][arow] = bv[j]; }
        __syncthreads();
#pragma unroll
        for (int kk = 0; kk < 16; kk++) {
            float4 a4 = *(const float4*)&As[kk][ty * 4];
            float4 b4 = *(const float4*)&Bs[kk][tx * 4];
            float ar[4] = {a4.x, a4.y, a4.z, a4.w};
            float br[4] = {b4.x, b4.y, b4.z, b4.w};
#pragma unroll
            for (int r = 0; r < 4; r++)
#pragma unroll
                for (int cc = 0; cc < 4; cc++) acc[r][cc] += ar[r] * br[cc];
        }
    }
#pragma unroll
    for (int r = 0; r < 4; r++) {
        int m = m0 + ty * 4 + r;
#pragma unroll
        for (int cc = 0; cc < 4; cc++) {
            int n = n0 + tx * 4 + cc;
            C[(size_t)m * G3 + n] = acc[r][cc] + bih[n];
        }
    }
}

// ============================================================================
// Kernel 2: sequential GRU scan, 32768 steps, 1 persistent CTA, 256 threads.
// Thread (i=t>>1, c=t&1) owns Whh rows {i,128+i,256+i}, cols [c*64, c*64+64).
// 192 weight regs/thread; packed FFMA2; single shfl.xor(1) reduce.
// Symmetric activation: c==0 lane -> pred output, c==1 lane -> state update.
// gi prefetched 4 steps ahead via cp.async into an 8-slot smem ring.
// ============================================================================
__global__ void __launch_bounds__(256, 1) gru_scan(
    const float* __restrict__ Whh, const float* __restrict__ bhh,
    const float* __restrict__ h0)
{
    __shared__ __align__(16) float hbuf[2][HH];
    __shared__ __align__(16) float gbuf[8][6 * HH];

    int t = threadIdx.x;
    int i = t >> 1;
    int c = t & 1;

    // Register-resident weights: 3 gates x 64 contiguous columns = 96 ull
    ull wr[32], wz[32], wn[32];
    {
        const ull* pr = (const ull*)(Whh + (size_t)i * HH + c * 64);
        const ull* pz = (const ull*)(Whh + (size_t)(HH + i) * HH + c * 64);
        const ull* pn = (const ull*)(Whh + (size_t)(2 * HH + i) * HH + c * 64);
#pragma unroll
        for (int q = 0; q < 32; q++) { wr[q] = pr[q]; wz[q] = pz[q]; wn[q] = pn[q]; }
    }
    float br = bhh[i], bz = bhh[HH + i], bn = bhh[2 * HH + i];
    if (t < HH) hbuf[0][t] = h0[t];

    // gi prefetch: c==0 -> pred triple at slot offset 0, c==1 -> true triple at 3*HH
    const float* srcbase = c ? (g_gi_true + i) : (g_gi_pred + i);
    unsigned gdst0 = (unsigned)__cvta_generic_to_shared(&gbuf[0][c * 3 * HH + i]);
    const unsigned BUFSTRIDE = 6 * HH * 4;   // 3072 bytes per ring slot

#pragma unroll
    for (int k = 0; k < 4; k++) {
        const float* sk = srcbase + (size_t)k * G3;
        unsigned d = gdst0 + (unsigned)k * BUFSTRIDE;
        cpa4(d, sk); cpa4(d + 512, sk + HH); cpa4(d + 1024, sk + 2 * HH);
        CP_COMMIT();
    }
    CP_WAIT3();
    __syncthreads();

    const float* srcnext = srcbase + 4 * (size_t)G3;
    int p = 0;

    for (int s = 0; s < NSTEP; s++) {
        // prefetch step s+4 into ring slot (s+4)&7
        if (s + 4 < NSTEP) {
            unsigned d = gdst0 + (unsigned)((s + 4) & 7) * BUFSTRIDE;
            cpa4(d, srcnext); cpa4(d + 512, srcnext + HH); cpa4(d + 1024, srcnext + 2 * HH);
        }
        CP_COMMIT();
        srcnext += G3;

        // gh partial over this thread's 64 columns (packed FFMA2)
        const ulonglong2* hp2 = (const ulonglong2*)(hbuf[p] + c * 64);
        ull ar = 0, az = 0, an = 0;
#pragma unroll
        for (int q = 0; q < 16; q++) {
            ulonglong2 hq = hp2[q];
            ar = ffma2(wr[2 * q],     hq.x, ar);
            az = ffma2(wz[2 * q],     hq.x, az);
            an = ffma2(wn[2 * q],     hq.x, an);
            ar = ffma2(wr[2 * q + 1], hq.y, ar);
            az = ffma2(wz[2 * q + 1], hq.y, az);
            an = ffma2(wn[2 * q + 1], hq.y, an);
        }
        float sr = plo(ar) + phi(ar);
        float sz = plo(az) + phi(az);
        float sn = plo(an) + phi(an);
        sr += __shfl_xor_sync(0xffffffffu, sr, 1);
        sz += __shfl_xor_sync(0xffffffffu, sz, 1);
        sn += __shfl_xor_sync(0xffffffffu, sn, 1);

        // Symmetric GRU update: c==0 uses pred gi (-> output), c==1 uses true gi (-> state)
        float ghr = sr + br, ghz = sz + bz, ghn = sn + bn;
        float hprev = hbuf[p][i];
        const float* gb = gbuf[s & 7] + c * 3 * HH;
        float r = sigf(gb[i] + ghr);
        float z = sigf(gb[HH + i] + ghz);
        float n = tanhf_fast(gb[2 * HH + i] + r * ghn);
        float hnew = (1.f - z) * n + z * hprev;
        if (c) hbuf[p ^ 1][i] = hnew;
        else   g_hpred[(size_t)s * HH + i] = hnew;

        CP_WAIT3();
        __syncthreads();
        p ^= 1;
    }
}

// ============================================================================
// Kernel 3: MLP head. 512 CTAs x 256 thr; 64 rows/CTA; fc1w smem-resident.
// ============================================================================
__global__ void __launch_bounds__(256) mlp_head(
    const float* __restrict__ fc1w, const float* __restrict__ fc1b,
    const float* __restrict__ fc2w, const float* __restrict__ fc2b,
    float* __restrict__ out)
{
    extern __shared__ float sm[];
    float* w1  = sm;
    float* b1  = sm + FCDIM * HH;
    float* w2  = b1 + FCDIM;
    float* hs  = w2 + FCDIM;
    float* red = hs + HH;

    int t = threadIdx.x;
    for (int idx = t; idx < FCDIM * HH; idx += 256) w1[idx] = fc1w[idx];
    b1[t] = fc1b[t];
    w2[t] = fc2w[t];
    __syncthreads();

    float myb = b1[t], myw2 = w2[t];
    const float4* wj = (const float4*)(w1 + t * HH);

    for (int r = 0; r < 64; r++) {
        size_t row = (size_t)blockIdx.x * 64 + r;
        if (t < HH) hs[t] = g_hpred[row * HH + t];
        __syncthreads();
        float acc = 0.f;
        const float4* hv = (const float4*)hs;
#pragma unroll
        for (int q = 0; q < 32; q++) {
            float4 a = wj[q], b = hv[q];
            acc += a.x * b.x; acc += a.y * b.y; acc += a.z * b.z; acc += a.w * b.w;
        }
        float v = acc + myb;
        v = v > 0.f ? v : 0.f;
        v *= myw2;
#pragma unroll
        for (int m = 16; m; m >>= 1) v += __shfl_xor_sync(0xffffffffu, v, m);
        if ((t & 31) == 0) red[t >> 5] = v;
        __syncthreads();
        if (t == 0) {
            float sv = red[0] + red[1] + red[2] + red[3] +
                       red[4] + red[5] + red[6] + red[7] + fc2b[0];
            out[row] = 1.f / (1.f + __expf(-sv));
        }
        __syncthreads();
    }
}

extern "C" void kernel_launch(void* const* d_in, const int* in_sizes, int n_in,
                              void* d_out, int out_size) {
    const float* enc  = (const float*)d_in[0];
    const float* act  = (const float*)d_in[1];
    const float* tru  = (const float*)d_in[2];
    const float* Wih  = (const float*)d_in[3];
    const float* Whh  = (const float*)d_in[4];
    const float* bih  = (const float*)d_in[5];
    const float* bhh  = (const float*)d_in[6];
    const float* h0   = (const float*)d_in[7];
    const float* fc1w = (const float*)d_in[8];
    const float* fc1b = (const float*)d_in[9];
    const float* fc2w = (const float*)d_in[10];
    const float* fc2b = (const float*)d_in[11];
    float* out = (float*)d_out;

    int mlp_smem = (FCDIM * HH + FCDIM + FCDIM + HH + 8) * 4;
    cudaFuncSetAttribute(mlp_head, cudaFuncAttributeMaxDynamicSharedMemorySize, mlp_smem);

    dim3 g(512, 6, 2);
    gi_gemm<<<g, 256>>>(enc, tru, act, Wih, bih);
    gru_scan<<<1, 256>>>(Whh, bhh, h0);
    mlp_head<<<512, 256, mlp_smem>>>(fc1w, fc1b, fc2w, fc2b, out);
}